// round 1
// baseline (speedup 1.0000x reference)
#include <cuda_runtime.h>
#include <cuda_bf16.h>
#include <cstdint>
#include <cstddef>

// Problem dims (fixed for this problem instance)
#define BS_TOTAL 4096   // B*S = 2*2048
#define D_DIM    1024
#define W_DIM    4096
#define NLEAF    8
#define C_DIM    11
#define SELP     80     // per-w packed selector: 64 weights + 8 biases + 8 pad

// ---------------- scratch (device globals: allowed, no cudaMalloc) ----------
__device__ float g_selp[W_DIM * SELP];                       // 1.3 MB
__device__ float g_slots[BS_TOTAL * 8];                      // 128 KB
__device__ __nv_bfloat16 g_rAh[(size_t)W_DIM * BS_TOTAL];    // roots hi, [w][bs]
__device__ __nv_bfloat16 g_rAl[(size_t)W_DIM * BS_TOTAL];    // roots lo, [w][bs]
__device__ __nv_bfloat16 g_wBh[(size_t)W_DIM * D_DIM];       // out_w hi, [k][n]
__device__ __nv_bfloat16 g_wBl[(size_t)W_DIM * D_DIM];       // out_w lo, [k][n]

// Accurate-enough tanh: 1 - 2/(exp(2x)+1) via ex2.approx + rcp.approx (~1e-6 err)
__device__ __forceinline__ float fast_tanh(float x) {
    float t = x * 2.885390081777926814f;   // 2*log2(e)
    float e;
    asm("ex2.approx.f32 %0, %1;" : "=f"(e) : "f"(t));
    float d = e + 1.0f;
    float r;
    asm("rcp.approx.f32 %0, %1;" : "=f"(r) : "f"(d));
    return fmaf(-2.0f, r, 1.0f);
}

// ---------------- K1a: selector softmax -> packed (weights + folded bias) ---
__global__ void k_sel(const float* __restrict__ logits) {
    int i = blockIdx.x * blockDim.x + threadIdx.x;   // (w*8 + l)
    if (i >= W_DIM * NLEAF) return;
    const float* p = logits + (size_t)i * C_DIM;
    float v[C_DIM];
#pragma unroll
    for (int c = 0; c < C_DIM; c++) v[c] = p[c];
    float m = v[0];
#pragma unroll
    for (int c = 1; c < C_DIM; c++) m = fmaxf(m, v[c]);
    float s = 0.0f;
#pragma unroll
    for (int c = 0; c < C_DIM; c++) { v[c] = __expf(v[c] - m); s += v[c]; }
    float r = 1.0f / s;
    int w = i >> 3, l = i & 7;
    float* o = g_selp + (size_t)w * SELP;
#pragma unroll
    for (int c = 0; c < 8; c++) o[l * 8 + c] = v[c] * r;
    // constants are (-1, 0, +1) at c = 8,9,10 -> folded bias
    o[64 + l] = (v[10] - v[8]) * r;
}

// ---------------- K1b: slots = tanh(hidden @ slot_w + slot_b) ---------------
__global__ void k_slots(const float* __restrict__ hidden,
                        const float* __restrict__ sw,
                        const float* __restrict__ sb) {
    int gwarp = (blockIdx.x * blockDim.x + threadIdx.x) >> 5;
    int lane = threadIdx.x & 31;
    if (gwarp >= BS_TOTAL) return;
    const float* h = hidden + (size_t)gwarp * D_DIM;
    float acc[8];
#pragma unroll
    for (int s = 0; s < 8; s++) acc[s] = 0.0f;
    for (int d0 = lane * 4; d0 < D_DIM; d0 += 128) {
        float4 hv = *(const float4*)(h + d0);
        const float* hvp = (const float*)&hv;
#pragma unroll
        for (int j = 0; j < 4; j++) {
            float hx = hvp[j];
            float4 w0 = *(const float4*)(sw + (size_t)(d0 + j) * 8);
            float4 w1 = *(const float4*)(sw + (size_t)(d0 + j) * 8 + 4);
            acc[0] = fmaf(hx, w0.x, acc[0]);
            acc[1] = fmaf(hx, w0.y, acc[1]);
            acc[2] = fmaf(hx, w0.z, acc[2]);
            acc[3] = fmaf(hx, w0.w, acc[3]);
            acc[4] = fmaf(hx, w1.x, acc[4]);
            acc[5] = fmaf(hx, w1.y, acc[5]);
            acc[6] = fmaf(hx, w1.z, acc[6]);
            acc[7] = fmaf(hx, w1.w, acc[7]);
        }
    }
#pragma unroll
    for (int off = 16; off > 0; off >>= 1) {
#pragma unroll
        for (int s = 0; s < 8; s++)
            acc[s] += __shfl_xor_sync(0xFFFFFFFFu, acc[s], off);
    }
    if (lane < 8)
        g_slots[(size_t)gwarp * 8 + lane] = fast_tanh(acc[lane] + sb[lane]);
}

// ---------------- K1c: split out_w into bf16 hi/lo (same [k][n] layout) -----
__global__ void k_wsplit(const float* __restrict__ ow) {
    int i = blockIdx.x * blockDim.x + threadIdx.x;
    if (i >= W_DIM * D_DIM) return;
    float x = ow[i];
    __nv_bfloat16 hv = __float2bfloat16(x);
    g_wBh[i] = hv;
    g_wBl[i] = __float2bfloat16(x - __bfloat162float(hv));
}

// ---------------- K2: fused einsum + tanh-tree -> roots (bf16 hi/lo) --------
#define K2_WT 64    // w per block
// block = 256 threads = 8 warps; each warp owns 32 consecutive bs rows
__global__ __launch_bounds__(256) void k_roots(const float* __restrict__ np) {
    __shared__ float s_sel[K2_WT * SELP];   // 20 KB

    int w0 = blockIdx.x * K2_WT;
    int bsblk = blockIdx.y * 256;
    int tid = threadIdx.x;

    // cooperative load of selector tile (contiguous region)
    {
        const float4* src = (const float4*)(g_selp + (size_t)w0 * SELP);
        float4* dst = (float4*)s_sel;
        for (int i = tid; i < K2_WT * SELP / 4; i += 256) dst[i] = src[i];
    }

    float lw = np[0], rw = np[1], pw = np[2], dw = np[3], nb = np[4];
    float ca = lw + dw, cb = rw - dw;

    int warp = tid >> 5, lane = tid & 31;
    int bs = bsblk + warp * 32 + lane;

    float4 s01 = *(const float4*)(g_slots + (size_t)bs * 8);
    float4 s23 = *(const float4*)(g_slots + (size_t)bs * 8 + 4);
    float s0 = s01.x, s1 = s01.y, s2 = s01.z, s3 = s01.w;
    float s4 = s23.x, s5 = s23.y, s6 = s23.z, s7 = s23.w;

    __syncthreads();

    for (int wi = 0; wi < K2_WT; wi++) {
        const float* sp = s_sel + wi * SELP;
        float4 bA = *(const float4*)(sp + 64);
        float4 bB = *(const float4*)(sp + 68);
        float bias[8] = {bA.x, bA.y, bA.z, bA.w, bB.x, bB.y, bB.z, bB.w};
        float v[8];
#pragma unroll
        for (int l = 0; l < 8; l++) {
            float4 w0v = *(const float4*)(sp + l * 8);
            float4 w1v = *(const float4*)(sp + l * 8 + 4);
            float t = bias[l];
            t = fmaf(w0v.x, s0, t);
            t = fmaf(w0v.y, s1, t);
            t = fmaf(w0v.z, s2, t);
            t = fmaf(w0v.w, s3, t);
            t = fmaf(w1v.x, s4, t);
            t = fmaf(w1v.y, s5, t);
            t = fmaf(w1v.z, s6, t);
            t = fmaf(w1v.w, s7, t);
            v[l] = t;
        }
        // 3-level binary tree on adjacent pairs
#pragma unroll
        for (int i = 0; i < 4; i++) {
            float L = v[2 * i], R = v[2 * i + 1];
            float u = fmaf(ca, L, nb);
            u = fmaf(cb, R, u);
            u = fmaf(pw, L * R, u);
            v[i] = fast_tanh(u);
        }
#pragma unroll
        for (int i = 0; i < 2; i++) {
            float L = v[2 * i], R = v[2 * i + 1];
            float u = fmaf(ca, L, nb);
            u = fmaf(cb, R, u);
            u = fmaf(pw, L * R, u);
            v[i] = fast_tanh(u);
        }
        {
            float L = v[0], R = v[1];
            float u = fmaf(ca, L, nb);
            u = fmaf(cb, R, u);
            u = fmaf(pw, L * R, u);
            v[0] = fast_tanh(u);
        }
        float root = v[0];
        __nv_bfloat16 hi = __float2bfloat16(root);
        float hif = __bfloat162float(hi);
        __nv_bfloat16 lo = __float2bfloat16(root - hif);
        size_t off = (size_t)(w0 + wi) * BS_TOTAL + bs;
        g_rAh[off] = hi;
        g_rAl[off] = lo;
    }
}

// ---------------- K3: C = roots @ out_w + out_b, split-bf16 (3 MMA products)
#define BM 128
#define BN 64
#define BK 32
#define NKT (W_DIM / BK)   // 128

#define LDMT(R0, R1, R2, R3, ADDR)                                          \
    asm volatile("ldmatrix.sync.aligned.m8n8.x4.trans.shared.b16 "          \
                 "{%0,%1,%2,%3}, [%4];"                                     \
                 : "=r"(R0), "=r"(R1), "=r"(R2), "=r"(R3) : "r"(ADDR))

#define MMA(C, A, B0, B1)                                                   \
    asm volatile("mma.sync.aligned.m16n8k16.row.col.f32.bf16.bf16.f32 "     \
                 "{%0,%1,%2,%3},{%4,%5,%6,%7},{%8,%9},{%0,%1,%2,%3};"       \
                 : "+f"(C[0]), "+f"(C[1]), "+f"(C[2]), "+f"(C[3])           \
                 : "r"(A[0]), "r"(A[1]), "r"(A[2]), "r"(A[3]),              \
                   "r"(B0), "r"(B1))

__global__ __launch_bounds__(256) void k_gemm(const float* __restrict__ outb,
                                              float* __restrict__ out) {
    __shared__ __nv_bfloat16 sAh[BK][BM + 8];
    __shared__ __nv_bfloat16 sAl[BK][BM + 8];
    __shared__ __nv_bfloat16 sBh[BK][BN + 8];
    __shared__ __nv_bfloat16 sBl[BK][BN + 8];

    int tid = threadIdx.x;
    int warp = tid >> 5, lane = tid & 31;
    int wm = warp >> 1, wn = warp & 1;
    int m0 = blockIdx.x * BM, n0 = blockIdx.y * BN;

    // global->reg staging indices
    int arow = tid >> 4;          // 0..15 (and +16)
    int acol = (tid & 15) * 8;
    int brow = tid >> 3;          // 0..31
    int bcol = (tid & 7) * 8;

    float acc[2][2][2][4];
#pragma unroll
    for (int a = 0; a < 2; a++)
#pragma unroll
        for (int b = 0; b < 2; b++)
#pragma unroll
            for (int c = 0; c < 2; c++)
#pragma unroll
                for (int d = 0; d < 4; d++) acc[a][b][c][d] = 0.0f;

    uint4 rah0, rah1, ral0, ral1, rbh, rbl;

#define LOAD_TILE(K0)                                                           \
    do {                                                                        \
        const __nv_bfloat16* pa =                                               \
            g_rAh + (size_t)((K0) + arow) * BS_TOTAL + m0 + acol;               \
        const __nv_bfloat16* pl =                                               \
            g_rAl + (size_t)((K0) + arow) * BS_TOTAL + m0 + acol;               \
        rah0 = *(const uint4*)pa;                                               \
        rah1 = *(const uint4*)(pa + (size_t)16 * BS_TOTAL);                     \
        ral0 = *(const uint4*)pl;                                               \
        ral1 = *(const uint4*)(pl + (size_t)16 * BS_TOTAL);                     \
        rbh = *(const uint4*)(g_wBh + (size_t)((K0) + brow) * D_DIM + n0 + bcol); \
        rbl = *(const uint4*)(g_wBl + (size_t)((K0) + brow) * D_DIM + n0 + bcol); \
    } while (0)

    // ldmatrix lane addressing (shared by A and B tiles)
    int kr = (lane & 7) | ((lane & 16) >> 1);   // k row within k16
    int off8 = (lane & 8);                      // 0 or 8 along m/n

    uint32_t baseAh = (uint32_t)__cvta_generic_to_shared(&sAh[0][0]);
    uint32_t baseAl = (uint32_t)__cvta_generic_to_shared(&sAl[0][0]);
    uint32_t baseBh = (uint32_t)__cvta_generic_to_shared(&sBh[0][0]);
    uint32_t baseBl = (uint32_t)__cvta_generic_to_shared(&sBl[0][0]);

    LOAD_TILE(0);

    for (int kt = 0; kt < NKT; kt++) {
        __syncthreads();
        *(uint4*)&sAh[arow][acol] = rah0;
        *(uint4*)&sAh[arow + 16][acol] = rah1;
        *(uint4*)&sAl[arow][acol] = ral0;
        *(uint4*)&sAl[arow + 16][acol] = ral1;
        *(uint4*)&sBh[brow][bcol] = rbh;
        *(uint4*)&sBl[brow][bcol] = rbl;
        __syncthreads();

        if (kt + 1 < NKT) LOAD_TILE((kt + 1) * BK);

#pragma unroll
        for (int ks = 0; ks < 2; ks++) {
            uint32_t ah[2][4], al[2][4], bh[2][4], bl[2][4];
#pragma unroll
            for (int mi = 0; mi < 2; mi++) {
                uint32_t moff =
                    ((ks * 16 + kr) * (BM + 8) + wm * 32 + mi * 16 + off8) * 2;
                LDMT(ah[mi][0], ah[mi][1], ah[mi][2], ah[mi][3], baseAh + moff);
                LDMT(al[mi][0], al[mi][1], al[mi][2], al[mi][3], baseAl + moff);
            }
#pragma unroll
            for (int nj = 0; nj < 2; nj++) {
                uint32_t noff =
                    ((ks * 16 + kr) * (BN + 8) + wn * 32 + nj * 16 + off8) * 2;
                LDMT(bh[nj][0], bh[nj][1], bh[nj][2], bh[nj][3], baseBh + noff);
                LDMT(bl[nj][0], bl[nj][1], bl[nj][2], bl[nj][3], baseBl + noff);
            }
#pragma unroll
            for (int mi = 0; mi < 2; mi++)
#pragma unroll
                for (int nj = 0; nj < 2; nj++)
#pragma unroll
                    for (int h = 0; h < 2; h++) {
                        // octet h of x4: {r_h, r_{h+2}}
                        MMA(acc[mi][nj][h], ah[mi], bh[nj][h], bh[nj][h + 2]);
                        MMA(acc[mi][nj][h], ah[mi], bl[nj][h], bl[nj][h + 2]);
                        MMA(acc[mi][nj][h], al[mi], bh[nj][h], bh[nj][h + 2]);
                    }
        }
    }

    // epilogue: += out_b, store fp32
    int g = lane >> 2;
    int t2 = (lane & 3) * 2;
#pragma unroll
    for (int mi = 0; mi < 2; mi++)
#pragma unroll
        for (int nj = 0; nj < 2; nj++)
#pragma unroll
            for (int h = 0; h < 2; h++) {
                int row = m0 + wm * 32 + mi * 16 + g;
                int col = n0 + wn * 32 + nj * 16 + h * 8 + t2;
                float b0 = outb[col];
                float b1 = outb[col + 1];
                float* p0 = out + (size_t)row * D_DIM + col;
                float* p1 = out + (size_t)(row + 8) * D_DIM + col;
                float2 v0 = {acc[mi][nj][h][0] + b0, acc[mi][nj][h][1] + b1};
                float2 v1 = {acc[mi][nj][h][2] + b0, acc[mi][nj][h][3] + b1};
                *(float2*)p0 = v0;
                *(float2*)p1 = v1;
            }
}

// ---------------- launch --------------------------------------------------
extern "C" void kernel_launch(void* const* d_in, const int* in_sizes, int n_in,
                              void* d_out, int out_size) {
    const float* hidden = (const float*)d_in[0];
    const float* slot_w = (const float*)d_in[1];
    const float* slot_b = (const float*)d_in[2];
    const float* leaf_logits = (const float*)d_in[3];
    const float* node_params = (const float*)d_in[4];
    const float* out_w = (const float*)d_in[5];
    const float* out_b = (const float*)d_in[6];
    float* out = (float*)d_out;

    (void)in_sizes; (void)n_in; (void)out_size;

    k_sel<<<(W_DIM * NLEAF + 255) / 256, 256>>>(leaf_logits);
    k_slots<<<(BS_TOTAL * 32 + 255) / 256, 256>>>(hidden, slot_w, slot_b);
    k_wsplit<<<(W_DIM * D_DIM + 255) / 256, 256>>>(out_w);
    k_roots<<<dim3(W_DIM / K2_WT, BS_TOTAL / 256), 256>>>(node_params);
    k_gemm<<<dim3(BS_TOTAL / BM, D_DIM / BN), 256>>>(out_b, out);
}

// round 4
// speedup vs baseline: 1.7589x; 1.7589x over previous
#include <cuda_runtime.h>
#include <cuda_fp16.h>
#include <cstdint>
#include <cstddef>

// Problem dims (fixed)
#define BS_TOTAL 4096
#define D_DIM    1024
#define W_DIM    4096
#define NLEAF    8
#define C_DIM    11
#define SELP     80

// ---------------- scratch (device globals) ----------------
__device__ float g_selp[W_DIM * SELP];
__device__ float g_slots[BS_TOTAL * 8];
__device__ __half g_rA[(size_t)W_DIM * BS_TOTAL];   // roots fp16, [k=w][m=bs]
__device__ __half g_wB[(size_t)W_DIM * D_DIM];      // out_w fp16, [k=w][n=d]

// tanh: 1 - 2/(exp(2x)+1) via ex2/rcp approx (~1e-6 abs err)
__device__ __forceinline__ float fast_tanh(float x) {
    float t = x * 2.885390081777926814f;
    float e;
    asm("ex2.approx.f32 %0, %1;" : "=f"(e) : "f"(t));
    float d = e + 1.0f;
    float r;
    asm("rcp.approx.f32 %0, %1;" : "=f"(r) : "f"(d));
    return fmaf(-2.0f, r, 1.0f);
}

// ---------------- K1a: softmax -> packed selector ----------------
__global__ void k_sel(const float* __restrict__ logits) {
    int i = blockIdx.x * blockDim.x + threadIdx.x;
    if (i >= W_DIM * NLEAF) return;
    const float* p = logits + (size_t)i * C_DIM;
    float v[C_DIM];
#pragma unroll
    for (int c = 0; c < C_DIM; c++) v[c] = p[c];
    float m = v[0];
#pragma unroll
    for (int c = 1; c < C_DIM; c++) m = fmaxf(m, v[c]);
    float s = 0.0f;
#pragma unroll
    for (int c = 0; c < C_DIM; c++) { v[c] = __expf(v[c] - m); s += v[c]; }
    float r = 1.0f / s;
    int w = i >> 3, l = i & 7;
    float* o = g_selp + (size_t)w * SELP;
#pragma unroll
    for (int c = 0; c < 8; c++) o[l * 8 + c] = v[c] * r;
    o[64 + l] = (v[10] - v[8]) * r;   // constants (-1,0,+1) folded into bias
}

// ---------------- K1b: slots = tanh(hidden @ slot_w + slot_b) ----------------
__global__ void k_slots(const float* __restrict__ hidden,
                        const float* __restrict__ sw,
                        const float* __restrict__ sb) {
    int gwarp = (blockIdx.x * blockDim.x + threadIdx.x) >> 5;
    int lane = threadIdx.x & 31;
    if (gwarp >= BS_TOTAL) return;
    const float* h = hidden + (size_t)gwarp * D_DIM;
    float acc[8];
#pragma unroll
    for (int s = 0; s < 8; s++) acc[s] = 0.0f;
    for (int d0 = lane * 4; d0 < D_DIM; d0 += 128) {
        float4 hv = *(const float4*)(h + d0);
        const float* hvp = (const float*)&hv;
#pragma unroll
        for (int j = 0; j < 4; j++) {
            float hx = hvp[j];
            float4 w0 = *(const float4*)(sw + (size_t)(d0 + j) * 8);
            float4 w1 = *(const float4*)(sw + (size_t)(d0 + j) * 8 + 4);
            acc[0] = fmaf(hx, w0.x, acc[0]);
            acc[1] = fmaf(hx, w0.y, acc[1]);
            acc[2] = fmaf(hx, w0.z, acc[2]);
            acc[3] = fmaf(hx, w0.w, acc[3]);
            acc[4] = fmaf(hx, w1.x, acc[4]);
            acc[5] = fmaf(hx, w1.y, acc[5]);
            acc[6] = fmaf(hx, w1.z, acc[6]);
            acc[7] = fmaf(hx, w1.w, acc[7]);
        }
    }
#pragma unroll
    for (int off = 16; off > 0; off >>= 1) {
#pragma unroll
        for (int s = 0; s < 8; s++)
            acc[s] += __shfl_xor_sync(0xFFFFFFFFu, acc[s], off);
    }
    if (lane < 8)
        g_slots[(size_t)gwarp * 8 + lane] = fast_tanh(acc[lane] + sb[lane]);
}

// ---------------- K1c: out_w fp32 -> fp16 (same [k][n] layout, no transpose)
__global__ void k_wconv(const float* __restrict__ ow) {
    int i = (blockIdx.x * blockDim.x + threadIdx.x) * 4;
    if (i >= W_DIM * D_DIM) return;
    float4 x = *(const float4*)(ow + i);
    __half2 a = __floats2half2_rn(x.x, x.y);
    __half2 b = __floats2half2_rn(x.z, x.w);
    *(__half2*)(g_wB + i) = a;
    *(__half2*)(g_wB + i + 2) = b;
}

// ---------------- K2: fused einsum + tanh tree -> roots fp16 [w][bs] --------
#define K2_WT 64
__global__ __launch_bounds__(256) void k_roots(const float* __restrict__ np) {
    __shared__ float s_sel[K2_WT * SELP];   // 20 KB

    int w0 = blockIdx.x * K2_WT;
    int bsblk = blockIdx.y * 256;
    int tid = threadIdx.x;

    {
        const float4* src = (const float4*)(g_selp + (size_t)w0 * SELP);
        float4* dst = (float4*)s_sel;
        for (int i = tid; i < K2_WT * SELP / 4; i += 256) dst[i] = src[i];
    }

    float lw = np[0], rw = np[1], pw = np[2], dw = np[3], nb = np[4];
    float ca = lw + dw, cb = rw - dw;

    int bs = bsblk + tid;

    float4 s01 = *(const float4*)(g_slots + (size_t)bs * 8);
    float4 s23 = *(const float4*)(g_slots + (size_t)bs * 8 + 4);
    float s0 = s01.x, s1 = s01.y, s2 = s01.z, s3 = s01.w;
    float s4 = s23.x, s5 = s23.y, s6 = s23.z, s7 = s23.w;

    __syncthreads();

    for (int wi = 0; wi < K2_WT; wi++) {
        const float* sp = s_sel + wi * SELP;
        float4 bA = *(const float4*)(sp + 64);
        float4 bB = *(const float4*)(sp + 68);
        float bias[8] = {bA.x, bA.y, bA.z, bA.w, bB.x, bB.y, bB.z, bB.w};
        float v[8];
#pragma unroll
        for (int l = 0; l < 8; l++) {
            float4 w0v = *(const float4*)(sp + l * 8);
            float4 w1v = *(const float4*)(sp + l * 8 + 4);
            float t = bias[l];
            t = fmaf(w0v.x, s0, t);
            t = fmaf(w0v.y, s1, t);
            t = fmaf(w0v.z, s2, t);
            t = fmaf(w0v.w, s3, t);
            t = fmaf(w1v.x, s4, t);
            t = fmaf(w1v.y, s5, t);
            t = fmaf(w1v.z, s6, t);
            t = fmaf(w1v.w, s7, t);
            v[l] = t;
        }
#pragma unroll
        for (int i = 0; i < 4; i++) {
            float L = v[2 * i], R = v[2 * i + 1];
            float u = fmaf(ca, L, nb);
            u = fmaf(cb, R, u);
            u = fmaf(pw, L * R, u);
            v[i] = fast_tanh(u);
        }
#pragma unroll
        for (int i = 0; i < 2; i++) {
            float L = v[2 * i], R = v[2 * i + 1];
            float u = fmaf(ca, L, nb);
            u = fmaf(cb, R, u);
            u = fmaf(pw, L * R, u);
            v[i] = fast_tanh(u);
        }
        float L = v[0], R = v[1];
        float u = fmaf(ca, L, nb);
        u = fmaf(cb, R, u);
        u = fmaf(pw, L * R, u);
        float root = fast_tanh(u);

        g_rA[(size_t)(w0 + wi) * BS_TOTAL + bs] = __float2half(root);
    }
}

// ---------------- K3: C = roots @ out_w + out_b  (single fp16 product) ------
// BM=128, BN=128, BK=32; 8 warps (2m x 4n), warp tile 64x32; 3-stage cp.async.
#define BM 128
#define BN 128
#define BK 32
#define NKT (W_DIM / BK)     // 128
#define NSTAGE 3
#define SA_PITCH (BM + 8)    // halves
#define SB_PITCH (BN + 8)
#define STG_HALVES (BK * SA_PITCH + BK * SB_PITCH)
#define G_SMEM (NSTAGE * STG_HALVES * 2)

__device__ __forceinline__ uint32_t smem_u32(const void* p) {
    uint32_t a;
    asm("{ .reg .u64 t; cvta.to.shared.u64 t, %1; cvt.u32.u64 %0, t; }"
        : "=r"(a) : "l"(p));
    return a;
}
__device__ __forceinline__ void cp16(uint32_t dst, const void* src) {
    asm volatile("cp.async.cg.shared.global [%0], [%1], 16;"
                 :: "r"(dst), "l"(src));
}
#define CP_COMMIT() asm volatile("cp.async.commit_group;" ::: "memory")
#define CP_WAIT(N)  asm volatile("cp.async.wait_group %0;" :: "n"(N) : "memory")

#define LDMT(R0, R1, R2, R3, ADDR)                                          \
    asm volatile("ldmatrix.sync.aligned.m8n8.x4.trans.shared.b16 "          \
                 "{%0,%1,%2,%3}, [%4];"                                     \
                 : "=r"(R0), "=r"(R1), "=r"(R2), "=r"(R3) : "r"(ADDR))

#define MMA(C, A, B0, B1)                                                   \
    asm volatile("mma.sync.aligned.m16n8k16.row.col.f32.f16.f16.f32 "       \
                 "{%0,%1,%2,%3},{%4,%5,%6,%7},{%8,%9},{%0,%1,%2,%3};"       \
                 : "+f"(C[0]), "+f"(C[1]), "+f"(C[2]), "+f"(C[3])           \
                 : "r"(A[0]), "r"(A[1]), "r"(A[2]), "r"(A[3]),              \
                   "r"(B0), "r"(B1))

__global__ __launch_bounds__(256, 2) void k_gemm(const float* __restrict__ outb,
                                                 float* __restrict__ out) {
    extern __shared__ __half smem[];

    int tid = threadIdx.x;
    int wid = tid >> 5, lane = tid & 31;
    int wm = wid >> 2, wn = wid & 3;       // 2 x 4 warp grid
    int m0 = blockIdx.x * BM, n0 = blockIdx.y * BN;

    // cp.async staging indices: 512 16B-chunks each for A and B per stage
    int ldrow = tid >> 4;        // 0..15 (+16)
    int ldcol = (tid & 15) * 8;  // halves

#define ISSUE_STAGE(ST, K0)                                                     \
    do {                                                                        \
        uint32_t sa = smem_u32(smem + (ST) * STG_HALVES);                       \
        uint32_t sbp = sa + BK * SA_PITCH * 2;                                  \
        _Pragma("unroll")                                                       \
        for (int i = 0; i < 2; i++) {                                           \
            int row = ldrow + i * 16;                                           \
            cp16(sa + (row * SA_PITCH + ldcol) * 2,                             \
                 g_rA + (size_t)((K0) + row) * BS_TOTAL + m0 + ldcol);          \
            cp16(sbp + (row * SB_PITCH + ldcol) * 2,                            \
                 g_wB + (size_t)((K0) + row) * D_DIM + n0 + ldcol);             \
        }                                                                       \
        CP_COMMIT();                                                            \
    } while (0)

    float acc[4][4][4];
#pragma unroll
    for (int a = 0; a < 4; a++)
#pragma unroll
        for (int b = 0; b < 4; b++)
#pragma unroll
            for (int c = 0; c < 4; c++) acc[a][b][c] = 0.0f;

    // ldmatrix lane addressing (R1-proven)
    int kr = (lane & 7) | ((lane & 16) >> 1);
    int off8 = (lane & 8);

    ISSUE_STAGE(0, 0);
    ISSUE_STAGE(1, BK);

    for (int kt = 0; kt < NKT; kt++) {
        CP_WAIT(1);
        __syncthreads();

        if (kt + 2 < NKT) ISSUE_STAGE((kt + 2) % NSTAGE, (kt + 2) * BK);

        uint32_t sa = smem_u32(smem + (kt % NSTAGE) * STG_HALVES);
        uint32_t sbp = sa + BK * SA_PITCH * 2;

#pragma unroll
        for (int ks = 0; ks < 2; ks++) {
            uint32_t a[4][4], b[2][4];
#pragma unroll
            for (int mi = 0; mi < 4; mi++) {
                uint32_t moff =
                    ((ks * 16 + kr) * SA_PITCH + wm * 64 + mi * 16 + off8) * 2;
                LDMT(a[mi][0], a[mi][1], a[mi][2], a[mi][3], sa + moff);
            }
#pragma unroll
            for (int nj2 = 0; nj2 < 2; nj2++) {
                uint32_t noff =
                    ((ks * 16 + kr) * SB_PITCH + wn * 32 + nj2 * 16 + off8) * 2;
                LDMT(b[nj2][0], b[nj2][1], b[nj2][2], b[nj2][3], sbp + noff);
            }
#pragma unroll
            for (int mi = 0; mi < 4; mi++)
#pragma unroll
                for (int nj2 = 0; nj2 < 2; nj2++)
#pragma unroll
                    for (int h = 0; h < 2; h++)
                        MMA(acc[mi][nj2 * 2 + h], a[mi], b[nj2][h], b[nj2][h + 2]);
        }
        __syncthreads();
    }

    // epilogue: += out_b, store fp32
    int g = lane >> 2;
    int t2 = (lane & 3) * 2;
#pragma unroll
    for (int mi = 0; mi < 4; mi++)
#pragma unroll
        for (int nj = 0; nj < 4; nj++) {
            int row = m0 + wm * 64 + mi * 16 + g;
            int col = n0 + wn * 32 + nj * 8 + t2;
            float b0 = outb[col];
            float b1 = outb[col + 1];
            float* p0 = out + (size_t)row * D_DIM + col;
            float* p1 = out + (size_t)(row + 8) * D_DIM + col;
            float2 v0 = {acc[mi][nj][0] + b0, acc[mi][nj][1] + b1};
            float2 v1 = {acc[mi][nj][2] + b0, acc[mi][nj][3] + b1};
            *(float2*)p0 = v0;
            *(float2*)p1 = v1;
        }
}

// ---------------- launch ----------------
extern "C" void kernel_launch(void* const* d_in, const int* in_sizes, int n_in,
                              void* d_out, int out_size) {
    const float* hidden = (const float*)d_in[0];
    const float* slot_w = (const float*)d_in[1];
    const float* slot_b = (const float*)d_in[2];
    const float* leaf_logits = (const float*)d_in[3];
    const float* node_params = (const float*)d_in[4];
    const float* out_w = (const float*)d_in[5];
    const float* out_b = (const float*)d_in[6];
    float* out = (float*)d_out;
    (void)in_sizes; (void)n_in; (void)out_size;

    cudaFuncSetAttribute(k_gemm, cudaFuncAttributeMaxDynamicSharedMemorySize, G_SMEM);

    k_sel<<<(W_DIM * NLEAF + 255) / 256, 256>>>(leaf_logits);
    k_slots<<<(BS_TOTAL * 32 + 255) / 256, 256>>>(hidden, slot_w, slot_b);
    k_wconv<<<(W_DIM * D_DIM / 4 + 255) / 256, 256>>>(out_w);
    k_roots<<<dim3(W_DIM / K2_WT, BS_TOTAL / 256), 256>>>(node_params);
    k_gemm<<<dim3(BS_TOTAL / BM, D_DIM / BN), 256, G_SMEM>>>(out_b, out);
}